// round 16
// baseline (speedup 1.0000x reference)
#include <cuda_runtime.h>
#include <math.h>

#define BATCH 2
#define LSEQ 256
#define CB 64
#define DMODEL 512
#define NHEAD 8
#define HD 64
#define NROWS (BATCH*LSEQ)   // 512
#define PSTR 68              // padded pair row stride (floats)
#define KSPLIT 8
#define KCHUNK (DMODEL/KSPLIT)   // 64
#define NBLK 128             // persistent grid size (<= 148 SMs -> all resident)

// Static scratch
__device__ float g_part [KSPLIT*NROWS*DMODEL];   // gemm1 partials (qk)
__device__ float g_part2[KSPLIT*NROWS*DMODEL];   // gemm2 partials (o) - separate: L1 aliasing
__device__ float g_wp[NROWS*DMODEL];
__device__ float g_Wqk[DMODEL*DMODEL];
__device__ float g_bqk[DMODEL];
__device__ float g_Wvo[DMODEL*DMODEL];
__device__ float g_bvo[DMODEL];

// Grid barrier state (monotonic phase; count resets each barrier)
__device__ unsigned g_bar_count = 0;
__device__ unsigned g_bar_phase = 0;

__device__ __forceinline__ void grid_barrier() {
    __syncthreads();
    if (threadIdx.x == 0) {
        __threadfence();
        unsigned ph = *(volatile unsigned*)&g_bar_phase;
        if (atomicAdd(&g_bar_count, 1u) == (unsigned)(NBLK - 1)) {
            g_bar_count = 0u;
            __threadfence();
            *(volatile unsigned*)&g_bar_phase = ph + 1u;
        } else {
            while (*(volatile unsigned*)&g_bar_phase == ph) { }
        }
        __threadfence();
    }
    __syncthreads();
}

// ---------------------------------------------------------------------------
// Phase bodies (all 256 threads)
// ---------------------------------------------------------------------------
__device__ void prep_body(int task, int tid, float* sm,
    const float* __restrict__ Wq, const float* __restrict__ bq,
    const float* __restrict__ Wk,
    const float* __restrict__ Wv, const float* __restrict__ bv,
    const float* __restrict__ Wo, const float* __restrict__ bo)
{
    float* Asm = sm;            // 64*68
    float* Bsm = sm + 64*68;    // 64*68
    const int tx = tid & 15;
    const int ty = tid >> 4;

    if (task < 64) {
        const int h = task >> 3, et = task & 7, e0 = et * 64;
        #pragma unroll
        for (int p = 0; p < 4; p++) {
            int f = tid + p*256; int e = f >> 4, d4 = f & 15;
            float4 v = *(const float4*)&Wq[(e0+e)*DMODEL + h*64 + d4*4];
            *(float4*)&Asm[e*68 + d4*4] = v;
        }
        #pragma unroll
        for (int p = 0; p < 4; p++) {
            int f = tid + p*256; int c = f >> 4, d4 = f & 15;
            float4 v = *(const float4*)&Wk[c*DMODEL + h*64 + d4*4];
            Bsm[(d4*4+0)*68 + c] = v.x; Bsm[(d4*4+1)*68 + c] = v.y;
            Bsm[(d4*4+2)*68 + c] = v.z; Bsm[(d4*4+3)*68 + c] = v.w;
        }
        __syncthreads();
        float acc[4][4] = {};
        #pragma unroll 8
        for (int d = 0; d < 64; d++) {
            float4 b = *(const float4*)&Bsm[d*68 + tx*4];
            #pragma unroll
            for (int rr = 0; rr < 4; rr++) {
                float a = Asm[(ty*4+rr)*68 + d];
                acc[rr][0] += a*b.x; acc[rr][1] += a*b.y;
                acc[rr][2] += a*b.z; acc[rr][3] += a*b.w;
            }
        }
        #pragma unroll
        for (int rr = 0; rr < 4; rr++) {
            float4 o;
            o.x = acc[rr][0]*0.125f; o.y = acc[rr][1]*0.125f;
            o.z = acc[rr][2]*0.125f; o.w = acc[rr][3]*0.125f;
            *(float4*)&g_Wqk[(e0 + ty*4+rr)*DMODEL + h*64 + tx*4] = o;
        }
        if (et == 0 && tid < 64) {
            float acc2 = 0.f;
            #pragma unroll 8
            for (int d = 0; d < 64; d++) acc2 += bq[h*64+d] * Bsm[d*68 + tid];
            g_bqk[h*64 + tid] = acc2 * 0.125f;
        }
    } else if (task < 128) {
        const int b2 = task - 64, h = b2 >> 3, nt = b2 & 7, n0 = nt * 64;
        #pragma unroll
        for (int p = 0; p < 4; p++) {
            int f = tid + p*256; int c = f >> 4, d4 = f & 15;
            float4 v = *(const float4*)&Wv[c*DMODEL + h*64 + d4*4];
            *(float4*)&Asm[c*68 + d4*4] = v;
        }
        #pragma unroll
        for (int p = 0; p < 4; p++) {
            int f = tid + p*256; int d = f >> 4, n4 = f & 15;
            float4 v = *(const float4*)&Wo[(h*64+d)*DMODEL + n0 + n4*4];
            *(float4*)&Bsm[d*68 + n4*4] = v;
        }
        __syncthreads();
        float acc[4][4] = {};
        #pragma unroll 8
        for (int d = 0; d < 64; d++) {
            float4 b = *(const float4*)&Bsm[d*68 + tx*4];
            #pragma unroll
            for (int rr = 0; rr < 4; rr++) {
                float a = Asm[(ty*4+rr)*68 + d];
                acc[rr][0] += a*b.x; acc[rr][1] += a*b.y;
                acc[rr][2] += a*b.z; acc[rr][3] += a*b.w;
            }
        }
        #pragma unroll
        for (int rr = 0; rr < 4; rr++) {
            float4 o;
            o.x = acc[rr][0]; o.y = acc[rr][1]; o.z = acc[rr][2]; o.w = acc[rr][3];
            *(float4*)&g_Wvo[(h*64 + ty*4+rr)*DMODEL + n0 + tx*4] = o;
        }
    } else {
        const int nb = task - 128, n0 = nb * 64;
        const int n = tid & 63, mg = tid >> 6;
        float acc = 0.f;
        for (int m = mg*128; m < mg*128 + 128; m++)
            acc += bv[m] * Wo[m*DMODEL + n0 + n];
        Asm[mg*64 + n] = acc;
        __syncthreads();
        if (tid < 64) {
            float s = Asm[tid] + Asm[64+tid] + Asm[128+tid] + Asm[192+tid] + bo[n0+tid];
            g_bvo[n0 + tid] = s;
        }
    }
    __syncthreads();
}

// GEMM tile: BM=64, BN=64, KCHUNK=64; 256 threads, 4x4/thread.
__device__ void gemm_body(int t, int tid, float* sm,
    const float* __restrict__ A, const float* __restrict__ W,
    float* __restrict__ Pbase)
{
    float* As = sm;             // [k][m] 64*68
    float* Bs = sm + 64*68;     // [k][n] 64*64
    const int bx = t & 7;
    const int by = (t >> 3) & 7;
    const int kz = t >> 6;
    const int tx = tid & 15;
    const int ty = tid >> 4;
    const int k0 = kz * KCHUNK;

    // A 64x64 -> transposed As[k][m]; 1024 f4, 4/thread
    #pragma unroll
    for (int p = 0; p < 4; p++) {
        int f = tid + p*256;
        int row = f >> 4, k4 = f & 15;
        float4 v = *(const float4*)&A[(by*64 + row)*DMODEL + k0 + k4*4];
        As[(k4*4+0)*68 + row] = v.x;
        As[(k4*4+1)*68 + row] = v.y;
        As[(k4*4+2)*68 + row] = v.z;
        As[(k4*4+3)*68 + row] = v.w;
    }
    // B 64x64; 1024 f4, 4/thread
    #pragma unroll
    for (int p = 0; p < 4; p++) {
        int f = tid + p*256;
        int row = f >> 4, n4 = f & 15;
        float4 v = *(const float4*)&W[(k0 + row)*DMODEL + bx*64 + n4*4];
        *(float4*)&Bs[row*64 + n4*4] = v;
    }
    __syncthreads();

    float acc[4][4] = {};
    #pragma unroll 8
    for (int k = 0; k < KCHUNK; k++) {
        float4 b = *(const float4*)&Bs[k*64 + tx*4];
        float4 a = *(const float4*)&As[k*68 + ty*4];
        acc[0][0] += a.x*b.x; acc[0][1] += a.x*b.y; acc[0][2] += a.x*b.z; acc[0][3] += a.x*b.w;
        acc[1][0] += a.y*b.x; acc[1][1] += a.y*b.y; acc[1][2] += a.y*b.z; acc[1][3] += a.y*b.w;
        acc[2][0] += a.z*b.x; acc[2][1] += a.z*b.y; acc[2][2] += a.z*b.z; acc[2][3] += a.z*b.w;
        acc[3][0] += a.w*b.x; acc[3][1] += a.w*b.y; acc[3][2] += a.w*b.z; acc[3][3] += a.w*b.w;
    }

    float* P = Pbase + (size_t)kz * NROWS * DMODEL;
    const int r0 = by*64 + ty*4;
    const int c0 = bx*64 + tx*4;
    #pragma unroll
    for (int rr = 0; rr < 4; rr++)
        *(float4*)&P[(r0+rr)*DMODEL + c0] = make_float4(acc[rr][0], acc[rr][1], acc[rr][2], acc[rr][3]);
    __syncthreads();
}

// Attention for one row; 256 threads. No max-pass (|s| small); 1/Z at end.
__device__ void attn_body(int row, int tid, float* sm, const float* __restrict__ pair)
{
    float* pairS = sm;                       // 256*68 = 17408 f
    float* qk_sm = sm + 256*PSTR;            // 512 f
    float* w_sm  = qk_sm + DMODEL;           // 2048 f
    float* red   = w_sm + 2048;              // 4096 f (warp sums then wp partials)
    float* zsum  = red + 4096;               // 8 f
    const int lane = tid & 31;
    const int warp = tid >> 5;

    const float4* pg = (const float4*)(pair + (size_t)row * (LSEQ*CB));
    #pragma unroll
    for (int it = 0; it < 16; it++) {
        int f = tid + it*256;
        int j = f >> 4, c4 = f & 15;
        float4 v = pg[f];
        *(float4*)&pairS[j*PSTR + c4*4] = v;
    }
    {
        float2 acc = *(const float2*)&g_bqk[tid*2];
        #pragma unroll
        for (int kz = 0; kz < KSPLIT; kz++) {
            float2 v = *(const float2*)&g_part[((size_t)kz*NROWS + row)*DMODEL + tid*2];
            acc.x += v.x; acc.y += v.y;
        }
        *(float2*)&qk_sm[tid*2] = acc;
    }
    __syncthreads();

    // Scores for this thread's j across all heads
    float s[NHEAD] = {};
    {
        const float4* prow = (const float4*)&pairS[tid*PSTR];
        #pragma unroll
        for (int c4 = 0; c4 < 16; c4++) {
            float4 p = prow[c4];
            #pragma unroll
            for (int h = 0; h < NHEAD; h++) {
                float4 q = *(const float4*)&qk_sm[h*64 + c4*4];
                s[h] += p.x*q.x + p.y*q.y + p.z*q.z + p.w*q.w;
            }
        }
    }
    float e[NHEAD];
    #pragma unroll
    for (int h = 0; h < NHEAD; h++) e[h] = __expf(s[h]);
    *(float4*)&w_sm[tid*8 + 0] = make_float4(e[0], e[1], e[2], e[3]);
    *(float4*)&w_sm[tid*8 + 4] = make_float4(e[4], e[5], e[6], e[7]);
    #pragma unroll
    for (int h = 0; h < NHEAD; h++) {
        float v = e[h];
        #pragma unroll
        for (int o = 16; o; o >>= 1) v += __shfl_xor_sync(0xffffffffu, v, o);
        if (lane == 0) red[warp*NHEAD + h] = v;
    }
    __syncthreads();
    if (tid < 8) {
        float v = 0.f;
        #pragma unroll
        for (int w = 0; w < 8; w++) v += red[w*NHEAD + tid];
        zsum[tid] = 1.0f / v;
    }
    __syncthreads();

    // wp partials: thread = (c4, jg of 16 j)
    {
        const int c4 = tid & 15, jg = tid >> 4;
        float4 acc[NHEAD];
        #pragma unroll
        for (int h = 0; h < NHEAD; h++) acc[h] = make_float4(0.f,0.f,0.f,0.f);
        #pragma unroll 4
        for (int jj = 0; jj < 16; jj++) {
            int j = jg*16 + jj;
            float4 p  = *(const float4*)&pairS[j*PSTR + c4*4];
            float4 wA = *(const float4*)&w_sm[j*8];
            float4 wB = *(const float4*)&w_sm[j*8 + 4];
            acc[0].x += wA.x*p.x; acc[0].y += wA.x*p.y; acc[0].z += wA.x*p.z; acc[0].w += wA.x*p.w;
            acc[1].x += wA.y*p.x; acc[1].y += wA.y*p.y; acc[1].z += wA.y*p.z; acc[1].w += wA.y*p.w;
            acc[2].x += wA.z*p.x; acc[2].y += wA.z*p.y; acc[2].z += wA.z*p.z; acc[2].w += wA.z*p.w;
            acc[3].x += wA.w*p.x; acc[3].y += wA.w*p.y; acc[3].z += wA.w*p.z; acc[3].w += wA.w*p.w;
            acc[4].x += wB.x*p.x; acc[4].y += wB.x*p.y; acc[4].z += wB.x*p.z; acc[4].w += wB.x*p.w;
            acc[5].x += wB.y*p.x; acc[5].y += wB.y*p.y; acc[5].z += wB.y*p.z; acc[5].w += wB.y*p.w;
            acc[6].x += wB.z*p.x; acc[6].y += wB.z*p.y; acc[6].z += wB.z*p.z; acc[6].w += wB.z*p.w;
            acc[7].x += wB.w*p.x; acc[7].y += wB.w*p.y; acc[7].z += wB.w*p.z; acc[7].w += wB.w*p.w;
        }
        // Fold adjacent j-groups (lane^16 flips jg parity, same c4)
        #pragma unroll
        for (int h = 0; h < NHEAD; h++) {
            acc[h].x += __shfl_xor_sync(0xffffffffu, acc[h].x, 16);
            acc[h].y += __shfl_xor_sync(0xffffffffu, acc[h].y, 16);
            acc[h].z += __shfl_xor_sync(0xffffffffu, acc[h].z, 16);
            acc[h].w += __shfl_xor_sync(0xffffffffu, acc[h].w, 16);
        }
        if ((jg & 1) == 0) {
            const int jg2 = jg >> 1;   // 0..7
            #pragma unroll
            for (int h = 0; h < NHEAD; h++)
                *(float4*)&red[(jg2*NHEAD + h)*64 + c4*4] = acc[h];
        }
    }
    __syncthreads();

    if (tid < 128) {
        const int h = tid >> 4, c4 = tid & 15;
        float4 sum = make_float4(0.f,0.f,0.f,0.f);
        #pragma unroll
        for (int jg2 = 0; jg2 < 8; jg2++) {
            float4 v = *(const float4*)&red[(jg2*NHEAD + h)*64 + c4*4];
            sum.x += v.x; sum.y += v.y; sum.z += v.z; sum.w += v.w;
        }
        float zi = zsum[h];
        sum.x *= zi; sum.y *= zi; sum.z *= zi; sum.w *= zi;
        *(float4*)&g_wp[row*DMODEL + h*64 + c4*4] = sum;
    }
    __syncthreads();
}

// LayerNorm for 2 rows (256 threads: 128 per row)
__device__ void ln_body(int rp, int tid, float* sm,
    const float* __restrict__ x, const float* __restrict__ gamma,
    const float* __restrict__ beta, float* __restrict__ out)
{
    float* rs = sm;   // 16 floats
    const int sub = tid >> 7;          // row within pair
    const int t   = tid & 127;
    const int row = rp*2 + sub;
    const int lane = t & 31, warp = t >> 5;

    float4 x4 = *(const float4*)&x[row*DMODEL + t*4];
    float4 b4v = *(const float4*)&g_bvo[t*4];
    float y0 = x4.x + b4v.x, y1 = x4.y + b4v.y, y2 = x4.z + b4v.z, y3 = x4.w + b4v.w;
    #pragma unroll
    for (int kz = 0; kz < KSPLIT; kz++) {
        float4 p4 = *(const float4*)&g_part2[((size_t)kz*NROWS + row)*DMODEL + t*4];
        y0 += p4.x; y1 += p4.y; y2 += p4.z; y3 += p4.w;
    }

    float sum = y0 + y1 + y2 + y3;
    float sq  = y0*y0 + y1*y1 + y2*y2 + y3*y3;
    #pragma unroll
    for (int o = 16; o; o >>= 1) {
        sum += __shfl_xor_sync(0xffffffffu, sum, o);
        sq  += __shfl_xor_sync(0xffffffffu, sq,  o);
    }
    if (lane == 0) { rs[sub*8 + warp] = sum; rs[sub*8 + 4 + warp] = sq; }
    __syncthreads();
    float ts = rs[sub*8+0] + rs[sub*8+1] + rs[sub*8+2] + rs[sub*8+3];
    float tq = rs[sub*8+4] + rs[sub*8+5] + rs[sub*8+6] + rs[sub*8+7];
    float mu  = ts * (1.0f/DMODEL);
    float var = tq * (1.0f/DMODEL) - mu*mu;
    float r = rsqrtf(var + 1e-5f);

    float4 g4 = *(const float4*)&gamma[t*4];
    float4 b4 = *(const float4*)&beta[t*4];
    float4 o_;
    o_.x = (y0 - mu)*r*g4.x + b4.x;
    o_.y = (y1 - mu)*r*g4.y + b4.y;
    o_.z = (y2 - mu)*r*g4.z + b4.z;
    o_.w = (y3 - mu)*r*g4.w + b4.w;
    *(float4*)&out[row*DMODEL + t*4] = o_;
    __syncthreads();
}

// ---------------------------------------------------------------------------
// Persistent fused kernel: 128 blocks x 256 threads, 5 phases, 4 grid barriers.
// ---------------------------------------------------------------------------
__global__ __launch_bounds__(256) void fused_kernel(
    const float* __restrict__ x, const float* __restrict__ pair,
    const float* __restrict__ Wq, const float* __restrict__ bq,
    const float* __restrict__ Wk,
    const float* __restrict__ Wv, const float* __restrict__ bv,
    const float* __restrict__ Wo, const float* __restrict__ bo,
    const float* __restrict__ gamma, const float* __restrict__ beta,
    float* __restrict__ out)
{
    extern __shared__ float sm[];
    const int bid = blockIdx.x;
    const int tid = threadIdx.x;

    // Phase 0: prep (136 tasks)
    for (int task = bid; task < 136; task += NBLK)
        prep_body(task, tid, sm, Wq, bq, Wk, Wv, bv, Wo, bo);
    grid_barrier();

    // Phase 1: gemm1 (qk partials), 512 tiles
    for (int t = bid; t < 512; t += NBLK)
        gemm_body(t, tid, sm, x, g_Wqk, g_part);
    grid_barrier();

    // Phase 2: attention, 512 rows
    for (int r = bid; r < 512; r += NBLK)
        attn_body(r, tid, sm, pair);
    grid_barrier();

    // Phase 3: gemm2 (o partials), 512 tiles
    for (int t = bid; t < 512; t += NBLK)
        gemm_body(t, tid, sm, g_wp, g_Wvo, g_part2);
    grid_barrier();

    // Phase 4: layernorm, 256 row-pairs
    for (int rp = bid; rp < 256; rp += NBLK)
        ln_body(rp, tid, sm, x, gamma, beta, out);
}

// ---------------------------------------------------------------------------
extern "C" void kernel_launch(void* const* d_in, const int* in_sizes, int n_in,
                              void* d_out, int out_size)
{
    const float* x     = (const float*)d_in[0];
    const float* pair  = (const float*)d_in[1];
    const float* Wq    = (const float*)d_in[2];
    const float* bq    = (const float*)d_in[3];
    const float* Wk    = (const float*)d_in[4];
    // bk (d_in[5]) is softmax-invariant (per-(row,h) constant), dropped
    const float* Wv    = (const float*)d_in[6];
    const float* bv    = (const float*)d_in[7];
    const float* Wo    = (const float*)d_in[8];
    const float* bo    = (const float*)d_in[9];
    const float* gamma = (const float*)d_in[10];
    const float* beta  = (const float*)d_in[11];
    float* out = (float*)d_out;

    const int FUSED_SMEM = (256*PSTR + DMODEL + 2048 + 4096 + 8) * 4;  // 96288 B
    cudaFuncSetAttribute(fused_kernel, cudaFuncAttributeMaxDynamicSharedMemorySize, FUSED_SMEM);

    fused_kernel<<<NBLK, 256, FUSED_SMEM>>>(
        x, pair, Wq, bq, Wk, Wv, bv, Wo, bo, gamma, beta, out);
}